// round 1
// baseline (speedup 1.0000x reference)
#include <cuda_runtime.h>
#include <cuda_bf16.h>

// Problem constants (from reference setup_inputs)
#define B_ 8
#define W_ 5
#define S_ 5
#define C_ 640
#define HW_ 100
#define Q_ 75
#define NK_ 5

// Scratch (static device allocations — allowed)
__device__ float g_sup_inv[B_ * W_ * C_];   // 1/||descriptors||_2 per (b,w,c)
__device__ float g_pn[B_ * W_ * C_];        // normalized prototypes
__device__ float g_qn[B_ * Q_ * C_];        // normalized query means
__device__ float g_qd_inv[B_ * Q_ * HW_];   // 1/||qd||_2 per (b,q,p)

__device__ __forceinline__ float warpSum(float v) {
    #pragma unroll
    for (int o = 16; o; o >>= 1) v += __shfl_xor_sync(0xffffffffu, v, o);
    return v;
}

// ---------------------------------------------------------------------------
// Kernel 1: support prep. grid = B*W, block = 256.
// sup_inv[b,w,c] = rsqrt( sum_{s,p} x^2 ), pn = normalize(mean_{s,p} x over c)
// ---------------------------------------------------------------------------
__global__ void prep_shot_kernel(const float* __restrict__ xs) {
    int bw = blockIdx.x;
    const float* base = xs + (size_t)bw * (S_ * C_ * HW_);
    __shared__ float s_proto[C_];

    for (int c = threadIdx.x; c < C_; c += blockDim.x) {
        float ss = 0.f, sm = 0.f;
        #pragma unroll
        for (int s = 0; s < S_; s++) {
            const float* p = base + ((size_t)s * C_ + c) * HW_;
            #pragma unroll 4
            for (int j = 0; j < HW_; j++) {
                float v = p[j];
                ss += v * v;
                sm += v;
            }
        }
        g_sup_inv[bw * C_ + c] = rsqrtf(ss);
        s_proto[c] = sm * (1.0f / (S_ * HW_));
    }
    __syncthreads();

    float local = 0.f;
    for (int c = threadIdx.x; c < C_; c += blockDim.x) {
        float v = s_proto[c];
        local += v * v;
    }
    local = warpSum(local);
    __shared__ float s_part[8];
    int wid = threadIdx.x >> 5, lid = threadIdx.x & 31;
    if (lid == 0) s_part[wid] = local;
    __syncthreads();
    __shared__ float s_inv;
    if (threadIdx.x == 0) {
        float t = 0.f;
        #pragma unroll
        for (int k = 0; k < 8; k++) t += s_part[k];
        s_inv = rsqrtf(t);
    }
    __syncthreads();
    for (int c = threadIdx.x; c < C_; c += blockDim.x)
        g_pn[bw * C_ + c] = s_proto[c] * s_inv;
}

// ---------------------------------------------------------------------------
// Kernel 2: query prep. grid = B*Q, block = 128.
// qn[b,q,c] = normalize_c(mean_p x); qd_inv[b,q,p] = rsqrt(sum_c x^2)
// ---------------------------------------------------------------------------
__global__ void prep_query_kernel(const float* __restrict__ xq) {
    int bq = blockIdx.x;
    const float* base = xq + (size_t)bq * (C_ * HW_);
    __shared__ float s_mean[C_];

    for (int c = threadIdx.x; c < C_; c += blockDim.x) {
        const float* p = base + (size_t)c * HW_;
        float sm = 0.f;
        #pragma unroll 4
        for (int j = 0; j < HW_; j++) sm += p[j];
        s_mean[c] = sm * (1.0f / HW_);
    }

    // per-position squared norms (threads 0..99, coalesced per row)
    if (threadIdx.x < HW_) {
        float sq = 0.f;
        #pragma unroll 4
        for (int c = 0; c < C_; c++) {
            float v = base[(size_t)c * HW_ + threadIdx.x];
            sq += v * v;
        }
        g_qd_inv[bq * HW_ + threadIdx.x] = rsqrtf(sq);
    }
    __syncthreads();

    float local = 0.f;
    for (int c = threadIdx.x; c < C_; c += blockDim.x) {
        float v = s_mean[c];
        local += v * v;
    }
    local = warpSum(local);
    __shared__ float s_part[4];
    int wid = threadIdx.x >> 5, lid = threadIdx.x & 31;
    if (lid == 0) s_part[wid] = local;
    __syncthreads();
    __shared__ float s_inv;
    if (threadIdx.x == 0) {
        float t = 0.f;
        #pragma unroll
        for (int k = 0; k < 4; k++) t += s_part[k];
        s_inv = rsqrtf(t);
    }
    __syncthreads();
    for (int c = threadIdx.x; c < C_; c += blockDim.x)
        g_qn[bq * C_ + c] = s_mean[c] * s_inv;
}

// ---------------------------------------------------------------------------
// Kernel 3: fused DN4 GEMM + top-k + cosine. grid = B*Q*W, block = 256.
// Per CTA: sim[100][500] = qd_n[100][640] * sup_n[500][640]^T, processed in
// 4 d-chunks of 128. Warp ty owns rows p = ty*13+i (i<13, p<100);
// lane tx owns d = chunk*128 + tx*4 + j (j<4). Top-5 per row extracted
// from registers via warp-argmax rounds; merged into running top-5 in smem.
// ---------------------------------------------------------------------------
#define TM 13
#define KB 16

__global__ void __launch_bounds__(256, 2)
dn4_main_kernel(const float* __restrict__ xq, const float* __restrict__ xs,
                const float* __restrict__ r_cos, const float* __restrict__ r_dn4,
                float* __restrict__ out) {
    int idx = blockIdx.x;
    int w = idx % W_;
    int q = (idx / W_) % Q_;
    int b = idx / (W_ * Q_);
    int tid = threadIdx.x;
    int tx = tid & 31;
    int ty = tid >> 5;

    __shared__ float sQ[KB][HW_ + 4];   // padded: rows p up to 103 read harmlessly
    __shared__ float sS[KB][132];
    __shared__ float run5[HW_][NK_];
    __shared__ float rbuf[2][8];

    // init running top-5
    for (int e = tid; e < HW_ * NK_; e += 256) run5[e / NK_][e % NK_] = -1e30f;

    const float* xq_b = xq + (size_t)(b * Q_ + q) * (C_ * HW_);
    const float* xs_b = xs + (size_t)(b * W_ + w) * (S_ * C_ * HW_);
    const float* supinv = g_sup_inv + (b * W_ + w) * C_;
    const float* qdinv = g_qd_inv + (b * Q_ + q) * HW_;

    int p0 = ty * TM;

    #pragma unroll 1
    for (int chunk = 0; chunk < 4; chunk++) {
        int d0 = chunk * 128;
        float acc[TM][4];
        #pragma unroll
        for (int i = 0; i < TM; i++)
            #pragma unroll
            for (int j = 0; j < 4; j++) acc[i][j] = 0.f;

        #pragma unroll 1
        for (int c0 = 0; c0 < C_; c0 += KB) {
            __syncthreads();
            // load query tile (scaled by qd_inv): KB x 100
            #pragma unroll
            for (int e = tid; e < KB * HW_; e += 256) {
                int kk = e / HW_;
                int p = e - kk * HW_;
                sQ[kk][p] = xq_b[(size_t)(c0 + kk) * HW_ + p] * qdinv[p];
            }
            // load support tile (scaled by sup_inv): KB x 128
            #pragma unroll
            for (int e = tid; e < KB * 128; e += 256) {
                int kk = e >> 7;
                int dd = e & 127;
                int d = d0 + dd;
                float v = 0.f;
                if (d < 500) {
                    int s = d / HW_;
                    int pp = d - s * HW_;
                    v = xs_b[((size_t)s * C_ + c0 + kk) * HW_ + pp] * supinv[c0 + kk];
                }
                sS[kk][dd] = v;
            }
            __syncthreads();

            #pragma unroll
            for (int kk = 0; kk < KB; kk++) {
                float4 s4 = *(const float4*)&sS[kk][tx * 4];
                float sv0 = s4.x, sv1 = s4.y, sv2 = s4.z, sv3 = s4.w;
                #pragma unroll
                for (int i = 0; i < TM; i++) {
                    float qv = sQ[kk][p0 + i];
                    acc[i][0] = fmaf(qv, sv0, acc[i][0]);
                    acc[i][1] = fmaf(qv, sv1, acc[i][1]);
                    acc[i][2] = fmaf(qv, sv2, acc[i][2]);
                    acc[i][3] = fmaf(qv, sv3, acc[i][3]);
                }
            }
        }

        // ---- top-k update for this d-chunk, straight from registers ----
        #pragma unroll 1
        for (int i = 0; i < TM; i++) {
            int p = p0 + i;
            if (p >= HW_) break;
            float v[4];
            #pragma unroll
            for (int j = 0; j < 4; j++) {
                int d = d0 + tx * 4 + j;
                v[j] = (d < 500) ? acc[i][j] : -1e30f;
            }
            // broadcast-read running top-5 (warp-private row)
            float r0 = run5[p][0], r1 = run5[p][1], r2 = run5[p][2],
                  r3 = run5[p][3], r4 = run5[p][4];
            #pragma unroll 1
            for (int round = 0; round < NK_; round++) {
                float lm = v[0]; int lj = 0;
                #pragma unroll
                for (int j = 1; j < 4; j++)
                    if (v[j] > lm) { lm = v[j]; lj = j; }
                float m = lm;
                #pragma unroll
                for (int o = 16; o; o >>= 1)
                    m = fmaxf(m, __shfl_xor_sync(0xffffffffu, m, o));
                // current running min
                float mn = r0; int mi = 0;
                if (r1 < mn) { mn = r1; mi = 1; }
                if (r2 < mn) { mn = r2; mi = 2; }
                if (r3 < mn) { mn = r3; mi = 3; }
                if (r4 < mn) { mn = r4; mi = 4; }
                if (m <= mn) break;  // remaining maxima can't improve
                if (mi == 0) r0 = m; else if (mi == 1) r1 = m;
                else if (mi == 2) r2 = m; else if (mi == 3) r3 = m; else r4 = m;
                // invalidate exactly one owner of m
                unsigned ballot = __ballot_sync(0xffffffffu, lm == m);
                int owner = __ffs(ballot) - 1;
                if (tx == owner) v[lj] = -1e30f;
            }
            if (tx == 0) {
                run5[p][0] = r0; run5[p][1] = r1; run5[p][2] = r2;
                run5[p][3] = r3; run5[p][4] = r4;
            }
            __syncwarp();
        }
    }
    __syncthreads();

    // ---- epilogue: dn4 sum + cosine dot, fused block reduce ----
    float dn4 = 0.f;
    for (int e = tid; e < HW_ * NK_; e += 256) dn4 += run5[e / NK_][e % NK_];
    float cosd = 0.f;
    const float* qn = g_qn + (b * Q_ + q) * C_;
    const float* pn = g_pn + (b * W_ + w) * C_;
    for (int c = tid; c < C_; c += 256) cosd += qn[c] * pn[c];

    dn4 = warpSum(dn4);
    cosd = warpSum(cosd);
    if (tx == 0) { rbuf[0][ty] = dn4; rbuf[1][ty] = cosd; }
    __syncthreads();
    if (tid == 0) {
        float a = 0.f, c2 = 0.f;
        #pragma unroll
        for (int k = 0; k < 8; k++) { a += rbuf[0][k]; c2 += rbuf[1][k]; }
        out[idx] = r_cos[0] * c2 + r_dn4[0] * (a * (1.0f / NK_));
    }
}

// ---------------------------------------------------------------------------
extern "C" void kernel_launch(void* const* d_in, const int* in_sizes, int n_in,
                              void* d_out, int out_size) {
    const float* x_shot  = (const float*)d_in[0];  // [8,5,5,640,10,10]
    const float* x_query = (const float*)d_in[1];  // [8,75,640,10,10]
    const float* r_cos   = (const float*)d_in[2];  // [1]
    const float* r_dn4   = (const float*)d_in[3];  // [1]
    float* out = (float*)d_out;                    // [8,75,5]

    prep_shot_kernel<<<B_ * W_, 256>>>(x_shot);
    prep_query_kernel<<<B_ * Q_, 128>>>(x_query);
    dn4_main_kernel<<<B_ * Q_ * W_, 256>>>(x_query, x_shot, r_cos, r_dn4, out);
}

// round 3
// speedup vs baseline: 3.5034x; 3.5034x over previous
#include <cuda_runtime.h>
#include <cuda_bf16.h>
#include <cstdint>

// Problem constants
#define B_ 8
#define W_ 5
#define S_ 5
#define C_ 640
#define HW_ 100
#define Q_ 75
#define NK_ 5

#define MT_ 59            // M-tiles of 128 over 7500 rows (padded to 7552)
#define MROWS_ 7500
#define K8_ 80            // K steps of 8 (C=640)
#define NPAD_ 512

// ---------------------------------------------------------------------------
// Scratch: __device__ globals (zero-initialized once; pad regions never
// written so they remain zero -> implicit zero padding).
// A layout: [b][mt][k8][mg(8)] tiles of 16x8 tf32 stored in m16n8k8 A-fragment
//   thread order: tile[t*4+reg], t=lane, reg=a0..a3.
// B layout: [bw][k8][n16(32)] tiles of 8x16 tf32 stored as paired B-fragments:
//   tile[t*4+reg] = [b0_lo, b1_lo, b0_hi, b1_hi] per lane.
// ---------------------------------------------------------------------------
__device__ float g_A[B_ * MT_ * K8_ * 8 * 128];       // 154.7 MB
__device__ float g_Bm[B_ * W_ * K8_ * 32 * 128];      // 52.4 MB
__device__ float g_rowsum[B_ * W_ * MROWS_];
__device__ float g_sup_inv[B_ * W_ * C_];
__device__ float g_proto[B_ * W_ * C_];
__device__ float g_pn[B_ * W_ * C_];
__device__ float g_qn[B_ * Q_ * C_];

__device__ __forceinline__ uint32_t f2tf32(float v) {
    uint32_t r;
    asm("cvt.rna.tf32.f32 %0, %1;" : "=r"(r) : "f"(v));
    return r;
}

__device__ __forceinline__ float warpSum(float v) {
    #pragma unroll
    for (int o = 16; o; o >>= 1) v += __shfl_xor_sync(0xffffffffu, v, o);
    return v;
}

__device__ __forceinline__ void mma8(float* d, uint4 a, uint32_t b0, uint32_t b1) {
    asm volatile(
        "mma.sync.aligned.m16n8k8.row.col.f32.tf32.tf32.f32 "
        "{%0,%1,%2,%3}, {%4,%5,%6,%7}, {%8,%9}, {%0,%1,%2,%3};"
        : "+f"(d[0]), "+f"(d[1]), "+f"(d[2]), "+f"(d[3])
        : "r"(a.x), "r"(a.y), "r"(a.z), "r"(a.w), "r"(b0), "r"(b1));
}

__device__ __forceinline__ void ins5(float (&t)[5], float v) {
    if (v > t[0]) {
        t[0] = v;
        if (t[0] > t[1]) { float x = t[1]; t[1] = t[0]; t[0] = x;
            if (t[1] > t[2]) { x = t[2]; t[2] = t[1]; t[1] = x;
                if (t[2] > t[3]) { x = t[3]; t[3] = t[2]; t[2] = x;
                    if (t[3] > t[4]) { x = t[4]; t[4] = t[3]; t[3] = x; } } } }
    }
}

// ---------------------------------------------------------------------------
// Kernel 1: per-(bw,c) support sums. One warp per (bw,c). grid=3200, block=256.
// ---------------------------------------------------------------------------
__global__ void prep_shot_sums(const float* __restrict__ xs) {
    int gw = blockIdx.x * 8 + (threadIdx.x >> 5);
    int lane = threadIdx.x & 31;
    int bw = gw / C_;
    int c = gw - bw * C_;
    const float* base = xs + (size_t)bw * (S_ * C_ * HW_);
    float ss = 0.f, sm = 0.f;
    for (int j = lane; j < S_ * HW_; j += 32) {
        int s = j / HW_;
        int p = j - s * HW_;
        float v = base[((size_t)s * C_ + c) * HW_ + p];
        ss += v * v;
        sm += v;
    }
    ss = warpSum(ss);
    sm = warpSum(sm);
    if (lane == 0) {
        g_sup_inv[bw * C_ + c] = rsqrtf(ss);
        g_proto[bw * C_ + c] = sm * (1.0f / (S_ * HW_));
    }
}

// Kernel 2: normalize prototypes. grid=40, block=256.
__global__ void prep_proto_norm() {
    int bw = blockIdx.x;
    int tid = threadIdx.x;
    float local = 0.f;
    for (int c = tid; c < C_; c += 256) {
        float v = g_proto[bw * C_ + c];
        local += v * v;
    }
    local = warpSum(local);
    __shared__ float part[8];
    if ((tid & 31) == 0) part[tid >> 5] = local;
    __syncthreads();
    __shared__ float sinv;
    if (tid == 0) {
        float t = 0.f;
        #pragma unroll
        for (int k = 0; k < 8; k++) t += part[k];
        sinv = rsqrtf(t);
    }
    __syncthreads();
    for (int c = tid; c < C_; c += 256)
        g_pn[bw * C_ + c] = g_proto[bw * C_ + c] * sinv;
}

// ---------------------------------------------------------------------------
// Kernel 3: pack A (query descriptors, scaled, tf32, fragment order)
// + fused query stats (qn). grid = B*Q = 600, block = 256.
// ---------------------------------------------------------------------------
#define CCH 64
__global__ void __launch_bounds__(256) packA(const float* __restrict__ xq) {
    int bq = blockIdx.x;
    int b = bq / Q_;
    int q = bq - b * Q_;
    int tid = threadIdx.x;
    const float* src = xq + (size_t)bq * (C_ * HW_);

    __shared__ float s_t[CCH][101];
    __shared__ float csum[C_];
    __shared__ float persq[HW_];
    __shared__ float qinv[HW_];
    __shared__ float part[8];
    __shared__ float sinv;

    for (int i = tid; i < C_; i += 256) csum[i] = 0.f;
    if (tid < HW_) persq[tid] = 0.f;
    __syncthreads();

    // pass 1: stats
    for (int cc0 = 0; cc0 < C_; cc0 += CCH) {
        for (int idx = tid; idx < CCH * HW_; idx += 256) {
            int cc = idx / HW_;
            int p = idx - cc * HW_;
            s_t[cc][p] = src[(size_t)(cc0 + cc) * HW_ + p];
        }
        __syncthreads();
        int wid = tid >> 5, lane = tid & 31;
        for (int cc = wid; cc < CCH; cc += 8) {
            float sm = 0.f;
            #pragma unroll
            for (int pp = lane; pp < HW_; pp += 32) sm += s_t[cc][pp];
            sm = warpSum(sm);
            if (lane == 0) csum[cc0 + cc] += sm;
        }
        if (tid < HW_) {
            float acc = 0.f;
            #pragma unroll 8
            for (int cc = 0; cc < CCH; cc++) {
                float v = s_t[cc][tid];
                acc += v * v;
            }
            persq[tid] += acc;
        }
        __syncthreads();
    }

    if (tid < HW_) qinv[tid] = rsqrtf(persq[tid]);
    float local = 0.f;
    for (int c = tid; c < C_; c += 256) {
        float m = csum[c] * (1.0f / HW_);
        local += m * m;
    }
    local = warpSum(local);
    if ((tid & 31) == 0) part[tid >> 5] = local;
    __syncthreads();
    if (tid == 0) {
        float t = 0.f;
        #pragma unroll
        for (int k = 0; k < 8; k++) t += part[k];
        sinv = rsqrtf(t);
    }
    __syncthreads();
    for (int c = tid; c < C_; c += 256)
        g_qn[bq * C_ + c] = csum[c] * (1.0f / HW_) * sinv;

    // pass 2: write scaled tf32 to g_A in fragment order
    for (int cc0 = 0; cc0 < C_; cc0 += CCH) {
        __syncthreads();
        for (int idx = tid; idx < CCH * HW_; idx += 256) {
            int cc = idx / HW_;
            int p = idx - cc * HW_;
            s_t[cc][p] = src[(size_t)(cc0 + cc) * HW_ + p];
        }
        __syncthreads();
        for (int idx = tid; idx < CCH * HW_; idx += 256) {
            int cc = idx & (CCH - 1);
            int p = idx >> 6;
            int c = cc0 + cc;
            int k8 = c >> 3;
            int c8 = c & 7;
            int r = q * HW_ + p;
            int mt = r >> 7;
            int rl = r & 127;
            int mg = rl >> 4;
            int rr = rl & 15;
            int t = (rr & 7) * 4 + (c8 & 3);
            int reg = (rr >> 3) | ((c8 >> 2) << 1);
            float v = s_t[cc][p] * qinv[p];
            g_A[((((size_t)(b * MT_ + mt) * K8_ + k8) * 8 + mg) << 7) + t * 4 + reg] =
                __uint_as_float(f2tf32(v));
        }
    }
}

// ---------------------------------------------------------------------------
// Kernel 4: pack B (support descriptors, scaled, tf32, fragment order).
// grid = B*W*S = 200, block = 256.
// ---------------------------------------------------------------------------
__global__ void __launch_bounds__(256) packB(const float* __restrict__ xs) {
    int bws = blockIdx.x;
    int s = bws % S_;
    int bw = bws / S_;
    int tid = threadIdx.x;
    const float* src = xs + (size_t)(bw * S_ + s) * (C_ * HW_);

    __shared__ float s_t[CCH][101];

    for (int cc0 = 0; cc0 < C_; cc0 += CCH) {
        __syncthreads();
        for (int idx = tid; idx < CCH * HW_; idx += 256) {
            int cc = idx / HW_;
            int p = idx - cc * HW_;
            s_t[cc][p] = src[(size_t)(cc0 + cc) * HW_ + p];
        }
        __syncthreads();
        for (int idx = tid; idx < CCH * HW_; idx += 256) {
            int cc = idx & (CCH - 1);
            int p = idx >> 6;
            int c = cc0 + cc;
            int k8 = c >> 3;
            int c8 = c & 7;
            int d = s * HW_ + p;          // 0..499
            int n16 = d >> 4;
            int nl = d & 15;
            int t = (nl & 7) * 4 + (c8 & 3);
            int reg = (c8 >> 2) | ((nl >> 3) << 1);
            float v = s_t[cc][p] * g_sup_inv[bw * C_ + c];
            g_Bm[((((size_t)bw * K8_ + k8) * 32 + n16) << 7) + t * 4 + reg] =
                __uint_as_float(f2tf32(v));
        }
    }
}

// ---------------------------------------------------------------------------
// Kernel 5: mma.sync tf32 GEMM + fused top-5. grid=(59,40), block=256.
// 8 warps: 4(M) x 2(N). CTA tile M=128, N=512 in 4 chunks of 128, K=640.
// ---------------------------------------------------------------------------
__global__ void __launch_bounds__(256) gemm_topk() {
    int mt = blockIdx.x;
    int bw = blockIdx.y;
    int b = bw / W_;
    int tid = threadIdx.x;
    int lane = tid & 31;
    int wid = tid >> 5;
    int wm = wid & 3;
    int wn = wid >> 2;

    const uint4* Ab = (const uint4*)(g_A + (((size_t)(b * MT_ + mt) * K8_) << 10));
    const uint4* Bb = (const uint4*)(g_Bm + (((size_t)bw * K8_) << 12));

    float t5[4][5];
    #pragma unroll
    for (int i = 0; i < 4; i++)
        #pragma unroll
        for (int s = 0; s < 5; s++) t5[i][s] = -1e30f;

    #pragma unroll 1
    for (int nc = 0; nc < 4; nc++) {
        float d[2][8][4];
        #pragma unroll
        for (int i = 0; i < 2; i++)
            #pragma unroll
            for (int j = 0; j < 8; j++)
                #pragma unroll
                for (int e = 0; e < 4; e++) d[i][j][e] = 0.f;

        int nb0 = nc * 8 + wn * 4;
        #pragma unroll 2
        for (int k8 = 0; k8 < K8_; k8++) {
            uint4 a0 = Ab[((k8 * 8 + wm * 2 + 0) << 5) + lane];
            uint4 a1 = Ab[((k8 * 8 + wm * 2 + 1) << 5) + lane];
            uint4 b0 = Bb[(((k8 << 5) + nb0 + 0) << 5) + lane];
            uint4 b1 = Bb[(((k8 << 5) + nb0 + 1) << 5) + lane];
            uint4 b2 = Bb[(((k8 << 5) + nb0 + 2) << 5) + lane];
            uint4 b3 = Bb[(((k8 << 5) + nb0 + 3) << 5) + lane];

            mma8(d[0][0], a0, b0.x, b0.y);  mma8(d[0][1], a0, b0.z, b0.w);
            mma8(d[0][2], a0, b1.x, b1.y);  mma8(d[0][3], a0, b1.z, b1.w);
            mma8(d[0][4], a0, b2.x, b2.y);  mma8(d[0][5], a0, b2.z, b2.w);
            mma8(d[0][6], a0, b3.x, b3.y);  mma8(d[0][7], a0, b3.z, b3.w);
            mma8(d[1][0], a1, b0.x, b0.y);  mma8(d[1][1], a1, b0.z, b0.w);
            mma8(d[1][2], a1, b1.x, b1.y);  mma8(d[1][3], a1, b1.z, b1.w);
            mma8(d[1][4], a1, b2.x, b2.y);  mma8(d[1][5], a1, b2.z, b2.w);
            mma8(d[1][6], a1, b3.x, b3.y);  mma8(d[1][7], a1, b3.z, b3.w);
        }

        // fold this n-chunk into per-thread top-5 (rows: i*2+h)
        int cbase = nc * 128 + wn * 64 + (lane & 3) * 2;
        #pragma unroll
        for (int i = 0; i < 2; i++)
            #pragma unroll
            for (int h = 0; h < 2; h++)
                #pragma unroll
                for (int j = 0; j < 8; j++)
                    #pragma unroll
                    for (int e = 0; e < 2; e++) {
                        int c = cbase + j * 8 + e;
                        float v = d[i][j][h * 2 + e];
                        if (c < 500) ins5(t5[i * 2 + h], v);
                    }
    }

    // merge per-row top-5 candidates via smem
    __shared__ float s5[128][42];
    int owner = wn * 4 + (lane & 3);   // 0..7
    #pragma unroll
    for (int i = 0; i < 2; i++)
        #pragma unroll
        for (int h = 0; h < 2; h++) {
            int rl = wm * 32 + i * 16 + h * 8 + (lane >> 2);
            #pragma unroll
            for (int s = 0; s < 5; s++)
                s5[rl][owner * 5 + s] = t5[i * 2 + h][s];
        }
    __syncthreads();

    if (tid < 128) {
        float t[5] = {-1e30f, -1e30f, -1e30f, -1e30f, -1e30f};
        #pragma unroll
        for (int s = 0; s < 40; s++) ins5(t, s5[tid][s]);
        int r = mt * 128 + tid;
        if (r < MROWS_)
            g_rowsum[(size_t)bw * MROWS_ + r] = t[0] + t[1] + t[2] + t[3] + t[4];
    }
}

// ---------------------------------------------------------------------------
// Kernel 6: finalize. grid = B*Q*W = 3000, block = 128.
// ---------------------------------------------------------------------------
__global__ void finalize(const float* __restrict__ r_cos, const float* __restrict__ r_dn4,
                         float* __restrict__ out) {
    int idx = blockIdx.x;
    int w = idx % W_;
    int q = (idx / W_) % Q_;
    int b = idx / (W_ * Q_);
    int tid = threadIdx.x;
    int bw = b * W_ + w;
    int bq = b * Q_ + q;

    float cosd = 0.f;
    for (int c = tid; c < C_; c += 128)
        cosd += g_qn[bq * C_ + c] * g_pn[bw * C_ + c];
    float dn4 = 0.f;
    if (tid < HW_)
        dn4 = g_rowsum[(size_t)bw * MROWS_ + q * HW_ + tid];

    cosd = warpSum(cosd);
    dn4 = warpSum(dn4);
    __shared__ float pc[4], pd[4];
    if ((tid & 31) == 0) { pc[tid >> 5] = cosd; pd[tid >> 5] = dn4; }
    __syncthreads();
    if (tid == 0) {
        float c2 = pc[0] + pc[1] + pc[2] + pc[3];
        float a = pd[0] + pd[1] + pd[2] + pd[3];
        out[idx] = r_cos[0] * c2 + r_dn4[0] * (a * (1.0f / NK_));
    }
}

// ---------------------------------------------------------------------------
extern "C" void kernel_launch(void* const* d_in, const int* in_sizes, int n_in,
                              void* d_out, int out_size) {
    const float* x_shot  = (const float*)d_in[0];
    const float* x_query = (const float*)d_in[1];
    const float* r_cos   = (const float*)d_in[2];
    const float* r_dn4   = (const float*)d_in[3];
    float* out = (float*)d_out;

    prep_shot_sums<<<3200, 256>>>(x_shot);
    prep_proto_norm<<<40, 256>>>();
    packA<<<B_ * Q_, 256>>>(x_query);
    packB<<<B_ * W_ * S_, 256>>>(x_shot);
    gemm_topk<<<dim3(MT_, B_ * W_), 256>>>();
    finalize<<<B_ * Q_ * W_, 128>>>(r_cos, r_dn4, out);
}

// round 4
// speedup vs baseline: 6.2534x; 1.7849x over previous
#include <cuda_runtime.h>
#include <cuda_fp16.h>
#include <cstdint>

// Problem constants
#define B_ 8
#define W_ 5
#define S_ 5
#define C_ 640
#define HW_ 100
#define Q_ 75
#define NK_ 5

#define MT_ 59            // M-tiles of 128 over 7500 rows (padded to 7552)
#define MROWS_ 7500
#define K16_ 40           // K steps of 16 (C=640)

// ---------------------------------------------------------------------------
// Scratch: __device__ globals (zero-init; pad regions never written -> zeros).
// A: [b][mt][k16][mg(8)] 16x16 fp16 tiles in m16n8k16 A-fragment order:
//    u32[lane*4 + reg], reg = a0..a3 (each u32 = half2).
// B: [bw][k16][n16(32)] paired 16x8 fp16 tiles:
//    u32[lane*4 + nsub*2 + reg], nsub = which n8 tile of the pair.
// ---------------------------------------------------------------------------
__device__ uint32_t g_A[B_ * MT_ * K16_ * 8 * 128];    // 77.3 MB
__device__ uint32_t g_Bm[B_ * W_ * K16_ * 32 * 128];   // 26.2 MB
__device__ float g_rowsum[B_ * W_ * MROWS_];
__device__ float g_sup_inv[B_ * W_ * C_];
__device__ float g_proto[B_ * W_ * C_];
__device__ float g_pn[B_ * W_ * C_];
__device__ float g_qn[B_ * Q_ * C_];

__device__ __forceinline__ float warpSum(float v) {
    #pragma unroll
    for (int o = 16; o; o >>= 1) v += __shfl_xor_sync(0xffffffffu, v, o);
    return v;
}

__device__ __forceinline__ void mma16(float* d, uint4 a, uint32_t b0, uint32_t b1) {
    asm volatile(
        "mma.sync.aligned.m16n8k16.row.col.f32.f16.f16.f32 "
        "{%0,%1,%2,%3}, {%4,%5,%6,%7}, {%8,%9}, {%0,%1,%2,%3};"
        : "+f"(d[0]), "+f"(d[1]), "+f"(d[2]), "+f"(d[3])
        : "r"(a.x), "r"(a.y), "r"(a.z), "r"(a.w), "r"(b0), "r"(b1));
}

__device__ __forceinline__ void ins5(float (&t)[5], float v) {
    if (v > t[0]) {
        t[0] = v;
        if (t[0] > t[1]) { float x = t[1]; t[1] = t[0]; t[0] = x;
            if (t[1] > t[2]) { x = t[2]; t[2] = t[1]; t[1] = x;
                if (t[2] > t[3]) { x = t[3]; t[3] = t[2]; t[2] = x;
                    if (t[3] > t[4]) { x = t[4]; t[4] = t[3]; t[3] = x; } } } }
    }
}

__device__ __forceinline__ uint32_t pack_h2(float v0, float v1) {
    __half2 h = __floats2half2_rn(v0, v1);   // .x (low) = v0
    return *(uint32_t*)&h;
}

// ---------------------------------------------------------------------------
// Kernel 1: per-(bw,c) support sums. One warp per (bw,c). grid=3200, block=256.
// ---------------------------------------------------------------------------
__global__ void prep_shot_sums(const float* __restrict__ xs) {
    int gw = blockIdx.x * 8 + (threadIdx.x >> 5);
    int lane = threadIdx.x & 31;
    int bw = gw / C_;
    int c = gw - bw * C_;
    const float* base = xs + (size_t)bw * (S_ * C_ * HW_);
    float ss = 0.f, sm = 0.f;
    for (int j = lane; j < S_ * HW_; j += 32) {
        int s = j / HW_;
        int p = j - s * HW_;
        float v = base[((size_t)s * C_ + c) * HW_ + p];
        ss += v * v;
        sm += v;
    }
    ss = warpSum(ss);
    sm = warpSum(sm);
    if (lane == 0) {
        g_sup_inv[bw * C_ + c] = rsqrtf(ss);
        g_proto[bw * C_ + c] = sm * (1.0f / (S_ * HW_));
    }
}

// Kernel 2: normalize prototypes. grid=40, block=256.
__global__ void prep_proto_norm() {
    int bw = blockIdx.x;
    int tid = threadIdx.x;
    float local = 0.f;
    for (int c = tid; c < C_; c += 256) {
        float v = g_proto[bw * C_ + c];
        local += v * v;
    }
    local = warpSum(local);
    __shared__ float part[8];
    if ((tid & 31) == 0) part[tid >> 5] = local;
    __syncthreads();
    __shared__ float sinv;
    if (tid == 0) {
        float t = 0.f;
        #pragma unroll
        for (int k = 0; k < 8; k++) t += part[k];
        sinv = rsqrtf(t);
    }
    __syncthreads();
    for (int c = tid; c < C_; c += 256)
        g_pn[bw * C_ + c] = g_proto[bw * C_ + c] * sinv;
}

// ---------------------------------------------------------------------------
// Kernel 3: pack A (query descriptors, scaled, fp16, fragment order)
// + fused query stats (qn). grid = B*Q = 600, block = 256.
// ---------------------------------------------------------------------------
#define CCH 64
__global__ void __launch_bounds__(256) packA(const float* __restrict__ xq) {
    int bq = blockIdx.x;
    int b = bq / Q_;
    int q = bq - b * Q_;
    int tid = threadIdx.x;
    const float* src = xq + (size_t)bq * (C_ * HW_);

    __shared__ float s_t[CCH][101];
    __shared__ float csum[C_];
    __shared__ float persq[HW_];
    __shared__ float qinv[HW_];
    __shared__ float part[8];
    __shared__ float sinv;

    for (int i = tid; i < C_; i += 256) csum[i] = 0.f;
    if (tid < HW_) persq[tid] = 0.f;
    __syncthreads();

    // pass 1: stats
    for (int cc0 = 0; cc0 < C_; cc0 += CCH) {
        for (int idx = tid; idx < CCH * HW_; idx += 256) {
            int cc = idx / HW_;
            int p = idx - cc * HW_;
            s_t[cc][p] = src[(size_t)(cc0 + cc) * HW_ + p];
        }
        __syncthreads();
        int wid = tid >> 5, lane = tid & 31;
        for (int cc = wid; cc < CCH; cc += 8) {
            float sm = 0.f;
            #pragma unroll
            for (int pp = lane; pp < HW_; pp += 32) sm += s_t[cc][pp];
            sm = warpSum(sm);
            if (lane == 0) csum[cc0 + cc] += sm;
        }
        if (tid < HW_) {
            float acc = 0.f;
            #pragma unroll 8
            for (int cc = 0; cc < CCH; cc++) {
                float v = s_t[cc][tid];
                acc += v * v;
            }
            persq[tid] += acc;
        }
        __syncthreads();
    }

    if (tid < HW_) qinv[tid] = rsqrtf(persq[tid]);
    float local = 0.f;
    for (int c = tid; c < C_; c += 256) {
        float m = csum[c] * (1.0f / HW_);
        local += m * m;
    }
    local = warpSum(local);
    if ((tid & 31) == 0) part[tid >> 5] = local;
    __syncthreads();
    if (tid == 0) {
        float t = 0.f;
        #pragma unroll
        for (int k = 0; k < 8; k++) t += part[k];
        sinv = rsqrtf(t);
    }
    __syncthreads();
    for (int c = tid; c < C_; c += 256)
        g_qn[bq * C_ + c] = csum[c] * (1.0f / HW_) * sinv;

    // pass 2: write scaled fp16 pairs to g_A in fragment order
    for (int cc0 = 0; cc0 < C_; cc0 += CCH) {
        __syncthreads();
        for (int idx = tid; idx < CCH * HW_; idx += 256) {
            int cc = idx / HW_;
            int p = idx - cc * HW_;
            s_t[cc][p] = src[(size_t)(cc0 + cc) * HW_ + p];
        }
        __syncthreads();
        for (int idx = tid; idx < (CCH / 2) * HW_; idx += 256) {
            int cc2 = idx & 31;
            int p = idx >> 5;
            int c = cc0 + cc2 * 2;        // even channel of the pair
            int k16 = c >> 4;
            int c16 = c & 15;             // even
            int r = q * HW_ + p;
            int mt = r >> 7;
            int rl = r & 127;
            int mg = rl >> 4;
            int rr = rl & 15;
            int tig = (c16 & 7) >> 1;
            int reg = (rr >> 3) | ((c16 >> 3) << 1);
            int lane = ((rr & 7) << 2) | tig;
            float v0 = s_t[cc2 * 2][p] * qinv[p];
            float v1 = s_t[cc2 * 2 + 1][p] * qinv[p];
            size_t tile = ((size_t)(b * MT_ + mt) * K16_ + k16) * 8 + mg;
            g_A[tile * 128 + lane * 4 + reg] = pack_h2(v0, v1);
        }
    }
}

// ---------------------------------------------------------------------------
// Kernel 4: pack B (support descriptors, scaled, fp16, fragment order).
// grid = B*W*S = 200, block = 256.
// ---------------------------------------------------------------------------
__global__ void __launch_bounds__(256) packB(const float* __restrict__ xs) {
    int bws = blockIdx.x;
    int s = bws % S_;
    int bw = bws / S_;
    int tid = threadIdx.x;
    const float* src = xs + (size_t)(bw * S_ + s) * (C_ * HW_);

    __shared__ float s_t[CCH][101];

    for (int cc0 = 0; cc0 < C_; cc0 += CCH) {
        __syncthreads();
        for (int idx = tid; idx < CCH * HW_; idx += 256) {
            int cc = idx / HW_;
            int p = idx - cc * HW_;
            s_t[cc][p] = src[(size_t)(cc0 + cc) * HW_ + p];
        }
        __syncthreads();
        for (int idx = tid; idx < (CCH / 2) * HW_; idx += 256) {
            int cc2 = idx & 31;
            int p = idx >> 5;
            int c = cc0 + cc2 * 2;
            int k16 = c >> 4;
            int c16 = c & 15;
            int d = s * HW_ + p;          // 0..499
            int n16 = d >> 4;
            int nsub = (d >> 3) & 1;
            int nl = d & 7;
            int tig = (c16 & 7) >> 1;
            int reg = c16 >> 3;
            int lane = (nl << 2) | tig;
            float v0 = s_t[cc2 * 2][p] * g_sup_inv[bw * C_ + c];
            float v1 = s_t[cc2 * 2 + 1][p] * g_sup_inv[bw * C_ + c + 1];
            size_t tile = ((size_t)bw * K16_ + k16) * 32 + n16;
            g_Bm[tile * 128 + lane * 4 + nsub * 2 + reg] = pack_h2(v0, v1);
        }
    }
}

// ---------------------------------------------------------------------------
// Kernel 5: mma.sync fp16 GEMM + fused top-5. grid=(59,40), block=256.
// 8 warps: 4(M) x 2(N). CTA tile M=128, N=512 in 4 chunks of 128, K=640.
// ---------------------------------------------------------------------------
__global__ void __launch_bounds__(256) gemm_topk() {
    int mt = blockIdx.x;
    int bw = blockIdx.y;
    int b = bw / W_;
    int tid = threadIdx.x;
    int lane = tid & 31;
    int wid = tid >> 5;
    int wm = wid & 3;
    int wn = wid >> 2;

    const uint4* Ab = (const uint4*)g_A + (size_t)(b * MT_ + mt) * (K16_ * 8 * 32);
    const uint4* Bb = (const uint4*)g_Bm + (size_t)bw * (K16_ * 32 * 32);

    float t5[4][5];
    #pragma unroll
    for (int i = 0; i < 4; i++)
        #pragma unroll
        for (int s = 0; s < 5; s++) t5[i][s] = -1e30f;

    #pragma unroll 1
    for (int nc = 0; nc < 4; nc++) {
        float d[2][8][4];
        #pragma unroll
        for (int i = 0; i < 2; i++)
            #pragma unroll
            for (int j = 0; j < 8; j++)
                #pragma unroll
                for (int e = 0; e < 4; e++) d[i][j][e] = 0.f;

        int nb0 = nc * 8 + wn * 4;        // pair-tile index base
        #pragma unroll 2
        for (int k = 0; k < K16_; k++) {
            uint4 a0 = Ab[((k * 8 + wm * 2 + 0) << 5) + lane];
            uint4 a1 = Ab[((k * 8 + wm * 2 + 1) << 5) + lane];
            uint4 b0 = Bb[(((k << 5) + nb0 + 0) << 5) + lane];
            uint4 b1 = Bb[(((k << 5) + nb0 + 1) << 5) + lane];
            uint4 b2 = Bb[(((k << 5) + nb0 + 2) << 5) + lane];
            uint4 b3 = Bb[(((k << 5) + nb0 + 3) << 5) + lane];

            mma16(d[0][0], a0, b0.x, b0.y);  mma16(d[0][1], a0, b0.z, b0.w);
            mma16(d[0][2], a0, b1.x, b1.y);  mma16(d[0][3], a0, b1.z, b1.w);
            mma16(d[0][4], a0, b2.x, b2.y);  mma16(d[0][5], a0, b2.z, b2.w);
            mma16(d[0][6], a0, b3.x, b3.y);  mma16(d[0][7], a0, b3.z, b3.w);
            mma16(d[1][0], a1, b0.x, b0.y);  mma16(d[1][1], a1, b0.z, b0.w);
            mma16(d[1][2], a1, b1.x, b1.y);  mma16(d[1][3], a1, b1.z, b1.w);
            mma16(d[1][4], a1, b2.x, b2.y);  mma16(d[1][5], a1, b2.z, b2.w);
            mma16(d[1][6], a1, b3.x, b3.y);  mma16(d[1][7], a1, b3.z, b3.w);
        }

        // fold this n-chunk into per-thread top-5 (rows: i*2+h)
        int cbase = nc * 128 + wn * 64 + (lane & 3) * 2;
        #pragma unroll
        for (int i = 0; i < 2; i++)
            #pragma unroll
            for (int h = 0; h < 2; h++)
                #pragma unroll
                for (int j = 0; j < 8; j++)
                    #pragma unroll
                    for (int e = 0; e < 2; e++) {
                        int c = cbase + j * 8 + e;
                        float v = d[i][j][h * 2 + e];
                        if (c < 500) ins5(t5[i * 2 + h], v);
                    }
    }

    // merge per-row top-5 candidates via smem
    __shared__ float s5[128][42];
    int owner = wn * 4 + (lane & 3);   // 0..7
    #pragma unroll
    for (int i = 0; i < 2; i++)
        #pragma unroll
        for (int h = 0; h < 2; h++) {
            int rl = wm * 32 + i * 16 + h * 8 + (lane >> 2);
            #pragma unroll
            for (int s = 0; s < 5; s++)
                s5[rl][owner * 5 + s] = t5[i * 2 + h][s];
        }
    __syncthreads();

    if (tid < 128) {
        float t[5] = {-1e30f, -1e30f, -1e30f, -1e30f, -1e30f};
        #pragma unroll
        for (int s = 0; s < 40; s++) ins5(t, s5[tid][s]);
        int r = mt * 128 + tid;
        if (r < MROWS_)
            g_rowsum[(size_t)bw * MROWS_ + r] = t[0] + t[1] + t[2] + t[3] + t[4];
    }
}

// ---------------------------------------------------------------------------
// Kernel 6: finalize. grid = B*Q*W = 3000, block = 128.
// ---------------------------------------------------------------------------
__global__ void finalize(const float* __restrict__ r_cos, const float* __restrict__ r_dn4,
                         float* __restrict__ out) {
    int idx = blockIdx.x;
    int w = idx % W_;
    int q = (idx / W_) % Q_;
    int b = idx / (W_ * Q_);
    int tid = threadIdx.x;
    int bw = b * W_ + w;
    int bq = b * Q_ + q;

    float cosd = 0.f;
    for (int c = tid; c < C_; c += 128)
        cosd += g_qn[bq * C_ + c] * g_pn[bw * C_ + c];
    float dn4 = 0.f;
    if (tid < HW_)
        dn4 = g_rowsum[(size_t)bw * MROWS_ + q * HW_ + tid];

    cosd = warpSum(cosd);
    dn4 = warpSum(dn4);
    __shared__ float pc[4], pd[4];
    if ((tid & 31) == 0) { pc[tid >> 5] = cosd; pd[tid >> 5] = dn4; }
    __syncthreads();
    if (tid == 0) {
        float c2 = pc[0] + pc[1] + pc[2] + pc[3];
        float a = pd[0] + pd[1] + pd[2] + pd[3];
        out[idx] = r_cos[0] * c2 + r_dn4[0] * (a * (1.0f / NK_));
    }
}

// ---------------------------------------------------------------------------
extern "C" void kernel_launch(void* const* d_in, const int* in_sizes, int n_in,
                              void* d_out, int out_size) {
    const float* x_shot  = (const float*)d_in[0];
    const float* x_query = (const float*)d_in[1];
    const float* r_cos   = (const float*)d_in[2];
    const float* r_dn4   = (const float*)d_in[3];
    float* out = (float*)d_out;

    prep_shot_sums<<<3200, 256>>>(x_shot);
    prep_proto_norm<<<40, 256>>>();
    packA<<<B_ * Q_, 256>>>(x_query);
    packB<<<B_ * W_ * S_, 256>>>(x_shot);
    gemm_topk<<<dim3(MT_, B_ * W_), 256>>>();
    finalize<<<B_ * Q_ * W_, 128>>>(r_cos, r_dn4, out);
}